// round 7
// baseline (speedup 1.0000x reference)
#include <cuda_runtime.h>
#include <cuda.h>
#include <cuda_bf16.h>
#include <cstdint>

// ---------------------------------------------------------------------------
// TPAsyncDense on tcgen05, persistent CTAs, 256x256 output tiles:
//   y[d] = sum_i x_i @ W[d,i] + b[d]
// 2-term bf16 split (v = hi + lo), fused 3-term product per K-chunk.
// 256x256 tile = 2 M-blocks x 2 N-halves of 128x128 MMAs sharing one SMEM
// B tile -> SMEM-fill traffic 6.44 GB -> 4.30 GB (L2/LTS was the binder).
// KB=32 (64B rows, SW64 swizzle), 3-stage TMA pipeline (64 KB/stage).
// Single 512-col TMEM accumulator (no ping-pong; TMA prefetch covers most
// of the epilogue bubble).
// ---------------------------------------------------------------------------

#if defined(__CUDA_ARCH_FEAT_SM103_ALL) || defined(__CUDA_ARCH_FEAT_SM100_ALL) || \
    defined(__CUDA_ARCH_SPECIFIC__) || defined(__CUDA_ARCH_FAMILY_SPECIFIC__)
#define TC_OK 1
#else
#define TC_OK 0
#endif

#define M_TOT 8192
#define N_TOT 2048
#define K_TOT 2048
#define D_TOT 4

#define BM 256
#define BN 256
#define KB 32                      // K elems per chunk (64B bf16 row = SW64)
#define NCHUNK 64                  // 2048 / 32
#define STAGES 3
#define NTILES (D_TOT * (M_TOT / BM) * (N_TOT / BN))   // 4*32*8 = 1024

// SMEM: header + 3 stages x {Ah 16K, Al 16K, Bh 16K, Bl 16K}
#define OFF_TMEM     0
#define OFF_FULL     16            // 3 x 8B
#define OFF_EMPTY    40            // 3 x 8B
#define OFF_ACCDONE  64
#define OFF_ACCFREE  72
#define OP_BYTES     (BM * 64)     // 16384 (256 rows x 64B)
#define STG_BYTES    (4 * OP_BYTES)                // 65536
#define OFF_STG      1024
#define SMEM_TOTAL   (OFF_STG + STAGES * STG_BYTES) // 197632
#define CHUNK_TX     STG_BYTES

// within a stage
#define SO_AH 0
#define SO_AL OP_BYTES
#define SO_BH (2 * OP_BYTES)
#define SO_BL (3 * OP_BYTES)

// idesc kind::f16: dtype=F32(1<<4), atype=BF16(1<<7), btype=BF16(1<<10),
// N=128 -> (128/8)<<17, M=128 -> (128/16)<<24
#define IDESC_N128 ((1u<<4) | (1u<<7) | (1u<<10) | (16u<<17) | (8u<<24))

// SW64 K-major smem descriptor base: layout=4 (SW64), version=1, SBO=32, LBO=1
// (atom = 8 rows x 64 B; SBO 32*16 = 512 B = 8 rows)
static constexpr uint64_t DESC_BASE_SW64 =
    (uint64_t(4) << 61) | (uint64_t(1) << 46) | (uint64_t(32) << 32) | (uint64_t(1) << 16);

// desc offsets (16B units): K-step (16 elems = 32B) -> +2 ; 128-row block
// (128 * 64B = 8192B) -> +512
#define DK 2
#define DBLK 512

// ------------------------- scratch (static device mem) ---------------------
__device__ __align__(1024) __nv_bfloat16 g_Ah[(size_t)M_TOT * K_TOT];
__device__ __align__(1024) __nv_bfloat16 g_Al[(size_t)M_TOT * K_TOT];
__device__ __align__(1024) __nv_bfloat16 g_Bh[(size_t)D_TOT * N_TOT * K_TOT];
__device__ __align__(1024) __nv_bfloat16 g_Bl[(size_t)D_TOT * N_TOT * K_TOT];

// ------------------------------ PTX helpers --------------------------------
__device__ __forceinline__ uint32_t smem_u32(const void* p) {
    uint32_t a;
    asm("{ .reg .u64 t; cvta.to.shared.u64 t, %1; cvt.u32.u64 %0, t; }" : "=r"(a) : "l"(p));
    return a;
}
__device__ __forceinline__ uint32_t elect_one() {
    uint32_t pred;
    asm volatile("{\n\t.reg .pred p;\n\telect.sync _|p, 0xFFFFFFFF;\n\tselp.b32 %0, 1, 0, p;\n\t}"
                 : "=r"(pred));
    return pred;
}
#define MBAR_INIT(addr, cnt) \
    asm volatile("mbarrier.init.shared.b64 [%0], %1;" :: "r"(addr), "r"(cnt) : "memory")
#define MBAR_INVAL(addr) \
    asm volatile("mbarrier.inval.shared.b64 [%0];" :: "r"(addr) : "memory")
#define MBAR_EXPECT_TX(addr, bytes) \
    asm volatile("mbarrier.arrive.expect_tx.shared.b64 _, [%0], %1;" :: "r"(addr), "r"(bytes) : "memory")
#define MBAR_ARRIVE(addr) \
    asm volatile("mbarrier.arrive.shared.b64 _, [%0];" :: "r"(addr) : "memory")

__device__ __forceinline__ void mbar_wait_acq(uint32_t mbar, uint32_t parity) {
    asm volatile(
        "{\n\t.reg .pred P1;\n\t"
        "WAIT_LOOP_%=:\n\t"
        "mbarrier.try_wait.parity.acquire.cta.shared::cta.b64 P1, [%0], %1, 0x989680;\n\t"
        "@P1 bra.uni WAIT_DONE_%=;\n\t"
        "bra.uni WAIT_LOOP_%=;\n\t"
        "WAIT_DONE_%=:\n\t}"
        :: "r"(mbar), "r"(parity) : "memory");
}
__device__ __forceinline__ void mbar_wait_rel(uint32_t mbar, uint32_t parity) {
    asm volatile(
        "{\n\t.reg .pred P1;\n\t"
        "WAIT_LOOP_%=:\n\t"
        "mbarrier.try_wait.parity.relaxed.cta.shared::cta.b64 P1, [%0], %1, 0x989680;\n\t"
        "@P1 bra.uni WAIT_DONE_%=;\n\t"
        "bra.uni WAIT_LOOP_%=;\n\t"
        "WAIT_DONE_%=:\n\t}"
        :: "r"(mbar), "r"(parity) : "memory");
}

__device__ __forceinline__ void tma_load_3d(uint32_t smem_dst, const CUtensorMap* map,
                                            int cx, int cy, int cz, uint32_t mbar) {
    asm volatile(
        "cp.async.bulk.tensor.3d.shared::cta.global.tile.mbarrier::complete_tx::bytes "
        "[%0], [%1, {%2, %3, %4}], [%5];"
        :: "r"(smem_dst), "l"(map), "r"(cx), "r"(cy), "r"(cz), "r"(mbar) : "memory");
}

#if TC_OK
__device__ __forceinline__ void mma_f16_ss(uint32_t dtm, uint64_t adesc, uint64_t bdesc,
                                           uint32_t idesc, uint32_t en) {
    asm volatile(
        "{\n\t.reg .pred p;\n\tsetp.ne.u32 p, %5, 0;\n\t"
        "tcgen05.mma.cta_group::1.kind::f16 [%0], %1, %2, %3, {%4, %4, %4, %4}, p;\n\t}"
        :: "r"(dtm), "l"(adesc), "l"(bdesc), "r"(idesc), "r"(0u), "r"(en) : "memory");
}

#define TC_ALLOC(smem_addr, cols) \
    asm volatile("tcgen05.alloc.cta_group::1.sync.aligned.shared::cta.b32 [%0], %1;" \
                 :: "r"(smem_addr), "r"(cols) : "memory")
#define TC_DEALLOC(tmem, cols) \
    asm volatile("tcgen05.dealloc.cta_group::1.sync.aligned.b32 %0, %1;" :: "r"(tmem), "r"(cols))
#define TC_RELINQ() \
    asm volatile("tcgen05.relinquish_alloc_permit.cta_group::1.sync.aligned;")
#define TC_COMMIT(mbar) \
    asm volatile("tcgen05.commit.cta_group::1.mbarrier::arrive::one.shared::cluster.b64 [%0];" \
                 :: "r"(mbar) : "memory")
#define TC_FENCE_AFTER() asm volatile("tcgen05.fence::after_thread_sync;" ::: "memory")
#define TC_FENCE_BEFORE() asm volatile("tcgen05.fence::before_thread_sync;" ::: "memory")
#define TC_WAIT_LD() asm volatile("tcgen05.wait::ld.sync.aligned;" ::: "memory")

#define TC_LD_X32(r, tm) \
    asm volatile( \
        "tcgen05.ld.sync.aligned.32x32b.x32.b32 " \
        "{%0, %1, %2, %3, %4, %5, %6, %7, " \
        " %8, %9, %10, %11, %12, %13, %14, %15, " \
        " %16, %17, %18, %19, %20, %21, %22, %23, " \
        " %24, %25, %26, %27, %28, %29, %30, %31}, [%32];" \
        : "=r"((r)[0]),  "=r"((r)[1]),  "=r"((r)[2]),  "=r"((r)[3]), \
          "=r"((r)[4]),  "=r"((r)[5]),  "=r"((r)[6]),  "=r"((r)[7]), \
          "=r"((r)[8]),  "=r"((r)[9]),  "=r"((r)[10]), "=r"((r)[11]), \
          "=r"((r)[12]), "=r"((r)[13]), "=r"((r)[14]), "=r"((r)[15]), \
          "=r"((r)[16]), "=r"((r)[17]), "=r"((r)[18]), "=r"((r)[19]), \
          "=r"((r)[20]), "=r"((r)[21]), "=r"((r)[22]), "=r"((r)[23]), \
          "=r"((r)[24]), "=r"((r)[25]), "=r"((r)[26]), "=r"((r)[27]), \
          "=r"((r)[28]), "=r"((r)[29]), "=r"((r)[30]), "=r"((r)[31]) \
        : "r"(tm))
#endif // TC_OK

// ------------------------------ prep kernels -------------------------------
__device__ __forceinline__ void split1(float v, unsigned short& h, unsigned short& l) {
    __nv_bfloat16 hb = __float2bfloat16_rn(v);
    float r = v - __bfloat162float(hb);
    __nv_bfloat16 lb = __float2bfloat16_rn(r);
    h = *reinterpret_cast<unsigned short*>(&hb);
    l = *reinterpret_cast<unsigned short*>(&lb);
}

// x: [4][8192][512] f32 -> Ah/Al: [8192][2048] bf16 (K = shard*512 + k)
__global__ void split_x_kernel(const float* __restrict__ x,
                               __nv_bfloat16* __restrict__ Ah,
                               __nv_bfloat16* __restrict__ Al) {
    size_t t = (size_t)blockIdx.x * blockDim.x + threadIdx.x;
    size_t e = t * 4;
    int i = (int)(e >> 22);
    int m = (int)((e >> 9) & 8191);
    int k = (int)(e & 511);
    float4 v = reinterpret_cast<const float4*>(x)[t];
    size_t o = (size_t)m * 2048 + i * 512 + k;
    ushort4 h, l;
    split1(v.x, h.x, l.x);
    split1(v.y, h.y, l.y);
    split1(v.z, h.z, l.z);
    split1(v.w, h.w, l.w);
    *reinterpret_cast<ushort4*>(Ah + o) = h;
    *reinterpret_cast<ushort4*>(Al + o) = l;
}

// W: [4][4][512][2048] (d,i,k,n) -> Bh/Bl: [4][2048(n)][2048(kg)] bf16 (transpose)
__global__ void split_w_kernel(const float* __restrict__ W,
                               __nv_bfloat16* __restrict__ Bh,
                               __nv_bfloat16* __restrict__ Bl) {
    __shared__ float tile[32][33];
    int di = blockIdx.z;
    int d = di >> 2, i = di & 3;
    int k0 = blockIdx.y * 32, n0 = blockIdx.x * 32;
    int tx = threadIdx.x, ty = threadIdx.y;   // 32 x 8
    const float* Wdi = W + (size_t)di * 512 * 2048;
#pragma unroll
    for (int j = 0; j < 32; j += 8)
        tile[ty + j][tx] = Wdi[(size_t)(k0 + ty + j) * 2048 + n0 + tx];
    __syncthreads();
    size_t obase = (size_t)d * 2048 * 2048;
#pragma unroll
    for (int j = 0; j < 32; j += 8) {
        float v = tile[tx][ty + j];
        unsigned short h, l;
        split1(v, h, l);
        size_t o = obase + (size_t)(n0 + ty + j) * 2048 + i * 512 + k0 + tx;
        *reinterpret_cast<unsigned short*>(Bh + o) = h;
        *reinterpret_cast<unsigned short*>(Bl + o) = l;
    }
}

// ------------------------------ GEMM kernel --------------------------------
__global__ __launch_bounds__(192, 1)
void tp_gemm_kernel(const __grid_constant__ CUtensorMap tmAh,
                    const __grid_constant__ CUtensorMap tmAl,
                    const __grid_constant__ CUtensorMap tmBh,
                    const __grid_constant__ CUtensorMap tmBl,
                    const float* __restrict__ bias,
                    float* __restrict__ out,
                    int gridSz) {
#if TC_OK
    extern __shared__ char smem[];
    const uint32_t sb = smem_u32(smem);
    const int tid = threadIdx.x;
    const int wid = tid >> 5;
    const int lid = tid & 31;
    const int bid = blockIdx.x;

    if (wid == 0) {
        TC_ALLOC(sb + OFF_TMEM, 512);
        TC_RELINQ();
    }
    if (tid == 0) {
#pragma unroll
        for (int s = 0; s < STAGES; s++) {
            MBAR_INIT(sb + OFF_FULL + 8 * s, 1);
            MBAR_INIT(sb + OFF_EMPTY + 8 * s, 1);
        }
        MBAR_INIT(sb + OFF_ACCDONE, 1);
        MBAR_INIT(sb + OFF_ACCFREE, 4);   // 4 epilogue warps
    }
    __syncthreads();

    uint32_t tmem;
    asm volatile("ld.shared.b32 %0, [%1];" : "=r"(tmem) : "r"(sb + OFF_TMEM));

    if (wid == 0) {
        // ---------------- producer: TMA loads ----------------
        int ps = 0; uint32_t pp = 1;          // empty-wait passes immediately
        for (int t = bid; t < NTILES; t += gridSz) {
            const int nIdx = t & 7;           // 2048/256 = 8 (fastest)
            const int mIdx = (t >> 3) & 31;   // 8192/256 = 32
            const int d    = t >> 8;
            const int mB = mIdx * BM;
            const int nB = nIdx * BN;
            for (int chunk = 0; chunk < NCHUNK; chunk++) {
                mbar_wait_rel(sb + OFF_EMPTY + 8 * ps, pp);
                if (elect_one()) {
                    const uint32_t fb = sb + OFF_FULL + 8 * ps;
                    const uint32_t stg = sb + OFF_STG + ps * STG_BYTES;
                    const int kc = chunk * KB;
                    MBAR_EXPECT_TX(fb, CHUNK_TX);
                    tma_load_3d(stg + SO_AH, &tmAh, kc, mB, 0, fb);
                    tma_load_3d(stg + SO_AL, &tmAl, kc, mB, 0, fb);
                    tma_load_3d(stg + SO_BH, &tmBh, kc, nB, d, fb);
                    tma_load_3d(stg + SO_BL, &tmBl, kc, nB, d, fb);
                }
                if (++ps == STAGES) { ps = 0; pp ^= 1; }
            }
        }
    } else if (wid == 1) {
        // ---------------- consumer: MMA issue ----------------
        int cs = 0; uint32_t cp = 0;
        uint32_t tIdx = 0;
        for (int t = bid; t < NTILES; t += gridSz, tIdx++) {
            // wait for epilogue to free the (single) accumulator
            mbar_wait_rel(sb + OFF_ACCFREE, (tIdx & 1) ^ 1);
            TC_FENCE_AFTER();
            for (int chunk = 0; chunk < NCHUNK; chunk++) {
                mbar_wait_acq(sb + OFF_FULL + 8 * cs, cp);
                if (elect_one()) {
                    const uint32_t stg = sb + OFF_STG + cs * STG_BYTES;
                    const uint64_t adh = DESC_BASE_SW64 | ((uint64_t)((stg + SO_AH) >> 4) & 0x3FFF);
                    const uint64_t adl = DESC_BASE_SW64 | ((uint64_t)((stg + SO_AL) >> 4) & 0x3FFF);
                    const uint64_t bdh = DESC_BASE_SW64 | ((uint64_t)((stg + SO_BH) >> 4) & 0x3FFF);
                    const uint64_t bdl = DESC_BASE_SW64 | ((uint64_t)((stg + SO_BL) >> 4) & 0x3FFF);
                    const uint64_t aseg[3] = {adh, adl, adh};
                    const uint64_t bseg[3] = {bdh, bdh, bdl};
#pragma unroll
                    for (int s3 = 0; s3 < 3; s3++) {
#pragma unroll
                        for (int ks = 0; ks < 2; ks++) {
                            const uint32_t en =
                                (chunk != 0 || s3 != 0 || ks != 0) ? 1u : 0u;
                            const uint64_t a0 = aseg[s3] + ks * DK;
                            const uint64_t a1 = aseg[s3] + DBLK + ks * DK;
                            const uint64_t b0 = bseg[s3] + ks * DK;
                            const uint64_t b1 = bseg[s3] + DBLK + ks * DK;
                            mma_f16_ss(tmem,       a0, b0, IDESC_N128, en);
                            mma_f16_ss(tmem + 128, a0, b1, IDESC_N128, en);
                            mma_f16_ss(tmem + 256, a1, b0, IDESC_N128, en);
                            mma_f16_ss(tmem + 384, a1, b1, IDESC_N128, en);
                        }
                    }
                    TC_COMMIT(sb + OFF_EMPTY + 8 * cs);
                    if (chunk == NCHUNK - 1)
                        TC_COMMIT(sb + OFF_ACCDONE);
                }
                if (++cs == STAGES) { cs = 0; cp ^= 1; }
            }
        }
    } else {
        // ---------------- epilogue: 4 warps (wid 2..5) ----------------
        // Warp's TMEM access goes through subpartition (wid & 3).
        const int sp = wid & 3;
        uint32_t tIdx = 0;
        for (int t = bid; t < NTILES; t += gridSz, tIdx++) {
            const int nIdx = t & 7;
            const int mIdx = (t >> 3) & 31;
            const int d    = t >> 8;
            const int mB = mIdx * BM;
            const int nB = nIdx * BN;

            mbar_wait_acq(sb + OFF_ACCDONE, tIdx & 1);
            TC_FENCE_AFTER();

            const int mRow0 = mB + sp * 32 + lid;         // mblock0 rows
            const int mRow1 = mRow0 + 128;                // mblock1 rows
            float* orow0 = out + ((size_t)d * M_TOT + mRow0) * N_TOT + nB;
            float* orow1 = out + ((size_t)d * M_TOT + mRow1) * N_TOT + nB;
            const float* brow = bias + d * N_TOT + nB;

            // cols 0..255 -> mblock0 (N 0..255); cols 256..511 -> mblock1
#pragma unroll
            for (int nb = 0; nb < 512; nb += 32) {
                uint32_t r[32];
                TC_LD_X32(r, tmem + nb);
                TC_WAIT_LD();
                const int ncol = nb & 255;
                float* orow = (nb < 256) ? orow0 : orow1;
#pragma unroll
                for (int j = 0; j < 32; j += 4) {
                    const float4 bv = *reinterpret_cast<const float4*>(brow + ncol + j);
                    float4 v;
                    v.x = __uint_as_float(r[j + 0]) + bv.x;
                    v.y = __uint_as_float(r[j + 1]) + bv.y;
                    v.z = __uint_as_float(r[j + 2]) + bv.z;
                    v.w = __uint_as_float(r[j + 3]) + bv.w;
                    *reinterpret_cast<float4*>(orow + ncol + j) = v;
                }
            }
            TC_FENCE_BEFORE();
            if (lid == 0)
                MBAR_ARRIVE(sb + OFF_ACCFREE);
        }
    }

    __syncthreads();
    if (tid == 0) {
#pragma unroll
        for (int s = 0; s < STAGES; s++) {
            MBAR_INVAL(sb + OFF_FULL + 8 * s);
            MBAR_INVAL(sb + OFF_EMPTY + 8 * s);
        }
        MBAR_INVAL(sb + OFF_ACCDONE);
        MBAR_INVAL(sb + OFF_ACCFREE);
    }
    __syncthreads();
    if (wid == 0) {
        TC_DEALLOC(tmem, 512);
    }
#endif // TC_OK
}

// ------------------------------ host launch --------------------------------
typedef CUresult (*PFN_encodeTiled)(CUtensorMap*, CUtensorMapDataType, cuuint32_t, void*,
                                    const cuuint64_t*, const cuuint64_t*, const cuuint32_t*,
                                    const cuuint32_t*, CUtensorMapInterleave, CUtensorMapSwizzle,
                                    CUtensorMapL2promotion, CUtensorMapFloatOOBfill);

static void make_map_bf16(PFN_encodeTiled enc, CUtensorMap* m, void* p,
                          uint64_t d0, uint64_t d1, uint64_t d2,
                          uint64_t s1b, uint64_t s2b, uint32_t b0, uint32_t b1) {
    cuuint64_t dims[3] = {d0, d1, d2};
    cuuint64_t strides[2] = {s1b, s2b};
    cuuint32_t box[3] = {b0, b1, 1};
    cuuint32_t es[3] = {1, 1, 1};
    enc(m, CU_TENSOR_MAP_DATA_TYPE_BFLOAT16, 3, p, dims, strides, box, es,
        CU_TENSOR_MAP_INTERLEAVE_NONE, CU_TENSOR_MAP_SWIZZLE_64B,
        CU_TENSOR_MAP_L2_PROMOTION_L2_128B, CU_TENSOR_MAP_FLOAT_OOB_FILL_NONE);
}

extern "C" void kernel_launch(void* const* d_in, const int* in_sizes, int n_in,
                              void* d_out, int out_size) {
    const float* x    = (const float*)d_in[0];
    const float* W    = (const float*)d_in[1];
    const float* bias = (const float*)d_in[2];
    float* out        = (float*)d_out;

    void *pAh, *pAl, *pBh, *pBl;
    cudaGetSymbolAddress(&pAh, g_Ah);
    cudaGetSymbolAddress(&pAl, g_Al);
    cudaGetSymbolAddress(&pBh, g_Bh);
    cudaGetSymbolAddress(&pBl, g_Bl);

    void* fp = nullptr;
    cudaDriverEntryPointQueryResult qr;
    cudaGetDriverEntryPoint("cuTensorMapEncodeTiled", &fp, cudaEnableDefault, &qr);
    PFN_encodeTiled enc = (PFN_encodeTiled)fp;

    CUtensorMap mAh, mAl, mBh, mBl;
    // A: dims {K=2048, M=8192, 1}; box {32, 256}
    make_map_bf16(enc, &mAh, pAh, K_TOT, M_TOT, 1,
                  (uint64_t)K_TOT * 2, (uint64_t)M_TOT * K_TOT * 2, KB, BM);
    make_map_bf16(enc, &mAl, pAl, K_TOT, M_TOT, 1,
                  (uint64_t)K_TOT * 2, (uint64_t)M_TOT * K_TOT * 2, KB, BM);
    // B: dims {K=2048, N=2048, D=4}; box {32, 256}
    make_map_bf16(enc, &mBh, pBh, K_TOT, N_TOT, D_TOT,
                  (uint64_t)K_TOT * 2, (uint64_t)N_TOT * K_TOT * 2, KB, BN);
    make_map_bf16(enc, &mBl, pBl, K_TOT, N_TOT, D_TOT,
                  (uint64_t)K_TOT * 2, (uint64_t)N_TOT * K_TOT * 2, KB, BN);

    split_x_kernel<<<(D_TOT * M_TOT * 512 / 4) / 256, 256>>>(
        x, (__nv_bfloat16*)pAh, (__nv_bfloat16*)pAl);
    split_w_kernel<<<dim3(2048 / 32, 512 / 32, 16), dim3(32, 8)>>>(
        W, (__nv_bfloat16*)pBh, (__nv_bfloat16*)pBl);

    int dev = 0, sms = 148;
    cudaGetDevice(&dev);
    cudaDeviceGetAttribute(&sms, cudaDevAttrMultiProcessorCount, dev);

    cudaFuncSetAttribute(tp_gemm_kernel, cudaFuncAttributeMaxDynamicSharedMemorySize,
                         SMEM_TOTAL);
    tp_gemm_kernel<<<sms, 192, SMEM_TOTAL>>>(mAh, mAl, mBh, mBl, bias, out, sms);
}

// round 8
// speedup vs baseline: 1.1703x; 1.1703x over previous
#include <cuda_runtime.h>
#include <cuda.h>
#include <cuda_bf16.h>
#include <cstdint>

// ---------------------------------------------------------------------------
// TPAsyncDense on tcgen05, persistent clusters (cta_group::2):
//   y[d] = sum_i x_i @ W[d,i] + b[d]
// 2-term bf16 split, fused 3-term product per K64 chunk.
// 2-CTA cluster computes a 256x256 tile: each CTA loads its own 128 M-rows of
// A and its own 128 N-rows of B (cg2 B-split), one cg2 N=256 MMA per k-step.
// Accumulator = 256 TMEM cols per CTA -> 2-buffer ping-pong (epilogue of tile
// t overlaps mainloop of tile t+1). 3-stage TMA pipeline, 64KB/stage/CTA.
// Traffic: 64KB/chunk/CTA vs 96KB in the 1-CTA 128x256 version (-33%).
// ---------------------------------------------------------------------------

#if defined(__CUDA_ARCH_FEAT_SM103_ALL) || defined(__CUDA_ARCH_FEAT_SM100_ALL) || \
    defined(__CUDA_ARCH_SPECIFIC__) || defined(__CUDA_ARCH_FAMILY_SPECIFIC__)
#define TC_OK 1
#else
#define TC_OK 0
#endif

#define M_TOT 8192
#define N_TOT 2048
#define K_TOT 2048
#define D_TOT 4

#define BM 256                     // per cluster (128 per CTA)
#define BN 256
#define KB 64                      // K elems per chunk (128B bf16 = SW128 row)
#define NCHUNK 32                  // 2048/64
#define STAGES 3
#define NTILES (D_TOT * (M_TOT / BM) * (N_TOT / BN))   // 4*32*8 = 1024

// SMEM per CTA: header + 3 stages x {Ah, Al, Bh, Bl} (16KB each)
#define OFF_TMEM     0
#define OFF_FULL     16            // 3 x 8B (leader-resident semantics)
#define OFF_EMPTY    40            // 3 x 8B
#define OFF_ACCDONE  64            // 2 x 8B
#define OFF_ACCFREE  80            // 2 x 8B (rank0's is the real one)
#define OP_BYTES     16384         // 128 rows x 128B
#define STG_BYTES    (4 * OP_BYTES)                 // 65536
#define OFF_STG      1024
#define SMEM_TOTAL   (OFF_STG + STAGES * STG_BYTES) // 197632
#define CHUNK_TX     (2 * STG_BYTES)                // both CTAs -> leader bar

#define SO_AH 0
#define SO_AL OP_BYTES
#define SO_BH (2 * OP_BYTES)
#define SO_BL (3 * OP_BYTES)

// idesc kind::f16 cg2: dtype=F32(1<<4), atype=BF16(1<<7), btype=BF16(1<<10),
// N=256 -> (256/8)<<17, M=256 -> (256/16)<<24
#define IDESC_CG2 ((1u<<4) | (1u<<7) | (1u<<10) | (32u<<17) | (16u<<24))

static constexpr uint64_t DESC_BASE_SW128 =
    (uint64_t(2) << 61) | (uint64_t(1) << 46) | (uint64_t(64) << 32) | (uint64_t(1) << 16);
#define DK 2                       // k-step 16 elems = 32B = 2 desc units

// ------------------------- scratch (static device mem) ---------------------
__device__ __align__(1024) __nv_bfloat16 g_Ah[(size_t)M_TOT * K_TOT];
__device__ __align__(1024) __nv_bfloat16 g_Al[(size_t)M_TOT * K_TOT];
__device__ __align__(1024) __nv_bfloat16 g_Bh[(size_t)D_TOT * N_TOT * K_TOT];
__device__ __align__(1024) __nv_bfloat16 g_Bl[(size_t)D_TOT * N_TOT * K_TOT];

// ------------------------------ PTX helpers --------------------------------
__device__ __forceinline__ uint32_t smem_u32(const void* p) {
    uint32_t a;
    asm("{ .reg .u64 t; cvta.to.shared.u64 t, %1; cvt.u32.u64 %0, t; }" : "=r"(a) : "l"(p));
    return a;
}
__device__ __forceinline__ uint32_t elect_one() {
    uint32_t pred;
    asm volatile("{\n\t.reg .pred p;\n\telect.sync _|p, 0xFFFFFFFF;\n\tselp.b32 %0, 1, 0, p;\n\t}"
                 : "=r"(pred));
    return pred;
}
__device__ __forceinline__ uint32_t cluster_rank() {
    uint32_t r;
    asm("mov.u32 %0, %%cluster_ctarank;" : "=r"(r));
    return r;
}
#define CLUSTER_SYNC() do { \
    asm volatile("barrier.cluster.arrive.aligned;" ::: "memory"); \
    asm volatile("barrier.cluster.wait.aligned;" ::: "memory"); \
} while (0)

#define MBAR_INIT(addr, cnt) \
    asm volatile("mbarrier.init.shared.b64 [%0], %1;" :: "r"(addr), "r"(cnt) : "memory")
#define MBAR_INVAL(addr) \
    asm volatile("mbarrier.inval.shared.b64 [%0];" :: "r"(addr) : "memory")
#define MBAR_EXPECT_TX(addr, bytes) \
    asm volatile("mbarrier.arrive.expect_tx.shared.b64 _, [%0], %1;" :: "r"(addr), "r"(bytes) : "memory")
// arrive on rank0's copy of a local mbarrier address
#define MBAR_ARRIVE_RANK0(addr) \
    asm volatile("{\n\t.reg .b32 ra;\n\tmapa.shared::cluster.u32 ra, %0, 0;\n\t" \
                 "mbarrier.arrive.shared::cluster.b64 _, [ra];\n\t}" \
                 :: "r"(addr) : "memory")

__device__ __forceinline__ void mbar_wait_acq(uint32_t mbar, uint32_t parity) {
    asm volatile(
        "{\n\t.reg .pred P1;\n\t"
        "WAIT_LOOP_%=:\n\t"
        "mbarrier.try_wait.parity.acquire.cta.shared::cta.b64 P1, [%0], %1, 0x989680;\n\t"
        "@P1 bra.uni WAIT_DONE_%=;\n\t"
        "bra.uni WAIT_LOOP_%=;\n\t"
        "WAIT_DONE_%=:\n\t}"
        :: "r"(mbar), "r"(parity) : "memory");
}
__device__ __forceinline__ void mbar_wait_rel(uint32_t mbar, uint32_t parity) {
    asm volatile(
        "{\n\t.reg .pred P1;\n\t"
        "WAIT_LOOP_%=:\n\t"
        "mbarrier.try_wait.parity.relaxed.cta.shared::cta.b64 P1, [%0], %1, 0x989680;\n\t"
        "@P1 bra.uni WAIT_DONE_%=;\n\t"
        "bra.uni WAIT_LOOP_%=;\n\t"
        "WAIT_DONE_%=:\n\t}"
        :: "r"(mbar), "r"(parity) : "memory");
}

#if TC_OK
// cg2 TMA: both CTAs execute; complete_tx targets rank0's barrier (bit 24 clear)
__device__ __forceinline__ void tma_load_cg2(uint32_t smem_dst, const CUtensorMap* map,
                                             int cx, int cy, int cz, uint32_t mbar) {
    asm volatile(
        "{\n\t.reg .b32 lb;\n\t"
        "and.b32 lb, %5, 0xFEFFFFFF;\n\t"
        "cp.async.bulk.tensor.3d.cta_group::2.shared::cluster.global"
        ".tile.mbarrier::complete_tx::bytes [%0], [%1, {%2, %3, %4}], [lb];\n\t}"
        :: "r"(smem_dst), "l"(map), "r"(cx), "r"(cy), "r"(cz), "r"(mbar) : "memory");
}

__device__ __forceinline__ void mma_f16_cg2(uint32_t dtm, uint64_t adesc, uint64_t bdesc,
                                            uint32_t idesc, uint32_t en) {
    asm volatile(
        "{\n\t.reg .pred p;\n\tsetp.ne.u32 p, %5, 0;\n\t"
        "tcgen05.mma.cta_group::2.kind::f16 [%0], %1, %2, %3, "
        "{%4, %4, %4, %4, %4, %4, %4, %4}, p;\n\t}"
        :: "r"(dtm), "l"(adesc), "l"(bdesc), "r"(idesc), "r"(0u), "r"(en) : "memory");
}

#define TC_ALLOC_CG2(smem_addr, cols) \
    asm volatile("tcgen05.alloc.cta_group::2.sync.aligned.shared::cta.b32 [%0], %1;" \
                 :: "r"(smem_addr), "r"(cols) : "memory")
#define TC_DEALLOC_CG2(tmem, cols) \
    asm volatile("tcgen05.dealloc.cta_group::2.sync.aligned.b32 %0, %1;" :: "r"(tmem), "r"(cols))
#define TC_RELINQ_CG2() \
    asm volatile("tcgen05.relinquish_alloc_permit.cta_group::2.sync.aligned;")
#define TC_COMMIT_MC_CG2(mbar) \
    asm volatile("tcgen05.commit.cta_group::2.mbarrier::arrive::one.shared::cluster" \
                 ".multicast::cluster.b64 [%0], %1;" \
                 :: "r"(mbar), "h"((uint16_t)0x3) : "memory")
#define TC_FENCE_AFTER() asm volatile("tcgen05.fence::after_thread_sync;" ::: "memory")
#define TC_FENCE_BEFORE() asm volatile("tcgen05.fence::before_thread_sync;" ::: "memory")
#define TC_WAIT_LD() asm volatile("tcgen05.wait::ld.sync.aligned;" ::: "memory")

#define TC_LD_X32(r, tm) \
    asm volatile( \
        "tcgen05.ld.sync.aligned.32x32b.x32.b32 " \
        "{%0, %1, %2, %3, %4, %5, %6, %7, " \
        " %8, %9, %10, %11, %12, %13, %14, %15, " \
        " %16, %17, %18, %19, %20, %21, %22, %23, " \
        " %24, %25, %26, %27, %28, %29, %30, %31}, [%32];" \
        : "=r"((r)[0]),  "=r"((r)[1]),  "=r"((r)[2]),  "=r"((r)[3]), \
          "=r"((r)[4]),  "=r"((r)[5]),  "=r"((r)[6]),  "=r"((r)[7]), \
          "=r"((r)[8]),  "=r"((r)[9]),  "=r"((r)[10]), "=r"((r)[11]), \
          "=r"((r)[12]), "=r"((r)[13]), "=r"((r)[14]), "=r"((r)[15]), \
          "=r"((r)[16]), "=r"((r)[17]), "=r"((r)[18]), "=r"((r)[19]), \
          "=r"((r)[20]), "=r"((r)[21]), "=r"((r)[22]), "=r"((r)[23]), \
          "=r"((r)[24]), "=r"((r)[25]), "=r"((r)[26]), "=r"((r)[27]), \
          "=r"((r)[28]), "=r"((r)[29]), "=r"((r)[30]), "=r"((r)[31]) \
        : "r"(tm))
#endif // TC_OK

// ------------------------------ prep kernels -------------------------------
__device__ __forceinline__ void split1(float v, unsigned short& h, unsigned short& l) {
    __nv_bfloat16 hb = __float2bfloat16_rn(v);
    float r = v - __bfloat162float(hb);
    __nv_bfloat16 lb = __float2bfloat16_rn(r);
    h = *reinterpret_cast<unsigned short*>(&hb);
    l = *reinterpret_cast<unsigned short*>(&lb);
}

// x: [4][8192][512] f32 -> Ah/Al: [8192][2048] bf16
__global__ void split_x_kernel(const float* __restrict__ x,
                               __nv_bfloat16* __restrict__ Ah,
                               __nv_bfloat16* __restrict__ Al) {
    size_t t = (size_t)blockIdx.x * blockDim.x + threadIdx.x;
    size_t e = t * 4;
    int i = (int)(e >> 22);
    int m = (int)((e >> 9) & 8191);
    int k = (int)(e & 511);
    float4 v = reinterpret_cast<const float4*>(x)[t];
    size_t o = (size_t)m * 2048 + i * 512 + k;
    ushort4 h, l;
    split1(v.x, h.x, l.x);
    split1(v.y, h.y, l.y);
    split1(v.z, h.z, l.z);
    split1(v.w, h.w, l.w);
    *reinterpret_cast<ushort4*>(Ah + o) = h;
    *reinterpret_cast<ushort4*>(Al + o) = l;
}

// W: [4][4][512][2048] (d,i,k,n) -> Bh/Bl: [4][2048(n)][2048(kg)] bf16
__global__ void split_w_kernel(const float* __restrict__ W,
                               __nv_bfloat16* __restrict__ Bh,
                               __nv_bfloat16* __restrict__ Bl) {
    __shared__ float tile[32][33];
    int di = blockIdx.z;
    int d = di >> 2, i = di & 3;
    int k0 = blockIdx.y * 32, n0 = blockIdx.x * 32;
    int tx = threadIdx.x, ty = threadIdx.y;   // 32 x 8
    const float* Wdi = W + (size_t)di * 512 * 2048;
#pragma unroll
    for (int j = 0; j < 32; j += 8)
        tile[ty + j][tx] = Wdi[(size_t)(k0 + ty + j) * 2048 + n0 + tx];
    __syncthreads();
    size_t obase = (size_t)d * 2048 * 2048;
#pragma unroll
    for (int j = 0; j < 32; j += 8) {
        float v = tile[tx][ty + j];
        unsigned short h, l;
        split1(v, h, l);
        size_t o = obase + (size_t)(n0 + ty + j) * 2048 + i * 512 + k0 + tx;
        *reinterpret_cast<unsigned short*>(Bh + o) = h;
        *reinterpret_cast<unsigned short*>(Bl + o) = l;
    }
}

// ------------------------------ GEMM kernel --------------------------------
__global__ __launch_bounds__(192, 1) __cluster_dims__(2, 1, 1)
void tp_gemm_kernel(const __grid_constant__ CUtensorMap tmAh,
                    const __grid_constant__ CUtensorMap tmAl,
                    const __grid_constant__ CUtensorMap tmBh,
                    const __grid_constant__ CUtensorMap tmBl,
                    const float* __restrict__ bias,
                    float* __restrict__ out,
                    int nClusters) {
#if TC_OK
    extern __shared__ char smem[];
    const uint32_t sb = smem_u32(smem);
    const int tid = threadIdx.x;
    const int wid = tid >> 5;
    const int lid = tid & 31;
    const uint32_t rank = cluster_rank();
    const int clu = (int)(blockIdx.x >> 1);

    if (wid == 0) {
        TC_ALLOC_CG2(sb + OFF_TMEM, 512);
        TC_RELINQ_CG2();
    }
    if (tid == 0) {
#pragma unroll
        for (int s = 0; s < STAGES; s++) {
            MBAR_INIT(sb + OFF_FULL + 8 * s, 1);
            MBAR_INIT(sb + OFF_EMPTY + 8 * s, 1);
        }
#pragma unroll
        for (int b = 0; b < 2; b++) {
            MBAR_INIT(sb + OFF_ACCDONE + 8 * b, 1);
            MBAR_INIT(sb + OFF_ACCFREE + 8 * b, 8);   // 4 warps x 2 CTAs
        }
    }
    __syncthreads();
    CLUSTER_SYNC();   // mbarriers visible cluster-wide before cg2 TMA/commit

    uint32_t tmem;
    asm volatile("ld.shared.b32 %0, [%1];" : "=r"(tmem) : "r"(sb + OFF_TMEM));

    if (wid == 0) {
        // ------- producer (both CTAs): cg2 TMA loads of own halves -------
        int ps = 0; uint32_t pp = 1;
        for (int t = clu; t < NTILES; t += nClusters) {
            const int nIdx = t & 7;
            const int mIdx = (t >> 3) & 31;
            const int d    = t >> 8;
            const int mRow = mIdx * BM + (int)rank * 128;   // own A half
            const int nRow = nIdx * BN + (int)rank * 128;   // own B half (cg2 split)
            for (int chunk = 0; chunk < NCHUNK; chunk++) {
                mbar_wait_rel(sb + OFF_EMPTY + 8 * ps, pp);
                if (elect_one()) {
                    const uint32_t fb = sb + OFF_FULL + 8 * ps;
                    const uint32_t stg = sb + OFF_STG + ps * STG_BYTES;
                    const int kc = chunk * KB;
                    if (rank == 0)
                        MBAR_EXPECT_TX(fb, CHUNK_TX);
                    tma_load_cg2(stg + SO_AH, &tmAh, kc, mRow, 0, fb);
                    tma_load_cg2(stg + SO_AL, &tmAl, kc, mRow, 0, fb);
                    tma_load_cg2(stg + SO_BH, &tmBh, kc, nRow, d, fb);
                    tma_load_cg2(stg + SO_BL, &tmBl, kc, nRow, d, fb);
                }
                if (++ps == STAGES) { ps = 0; pp ^= 1; }
            }
        }
    } else if (wid == 1 && rank == 0) {
        // ------- consumer (rank 0 only): cg2 MMA issue -------
        int cs = 0; uint32_t cp = 0;
        uint32_t tIdx = 0;
        for (int t = clu; t < NTILES; t += nClusters, tIdx++) {
            const int b = tIdx & 1;
            mbar_wait_rel(sb + OFF_ACCFREE + 8 * b, ((tIdx >> 1) & 1) ^ 1);
            TC_FENCE_AFTER();
            const uint32_t dtm = tmem + b * 256;
            for (int chunk = 0; chunk < NCHUNK; chunk++) {
                mbar_wait_acq(sb + OFF_FULL + 8 * cs, cp);
                if (elect_one()) {
                    const uint32_t stg = sb + OFF_STG + cs * STG_BYTES;
                    const uint64_t adh = DESC_BASE_SW128 | ((uint64_t)((stg + SO_AH) >> 4) & 0x3FFF);
                    const uint64_t adl = DESC_BASE_SW128 | ((uint64_t)((stg + SO_AL) >> 4) & 0x3FFF);
                    const uint64_t bdh = DESC_BASE_SW128 | ((uint64_t)((stg + SO_BH) >> 4) & 0x3FFF);
                    const uint64_t bdl = DESC_BASE_SW128 | ((uint64_t)((stg + SO_BL) >> 4) & 0x3FFF);
                    const uint64_t aseg[3] = {adh, adl, adh};
                    const uint64_t bseg[3] = {bdh, bdh, bdl};
#pragma unroll
                    for (int s3 = 0; s3 < 3; s3++) {
#pragma unroll
                        for (int ks = 0; ks < 4; ks++) {
                            const uint32_t en =
                                (chunk != 0 || s3 != 0 || ks != 0) ? 1u : 0u;
                            mma_f16_cg2(dtm, aseg[s3] + ks * DK, bseg[s3] + ks * DK,
                                        IDESC_CG2, en);
                        }
                    }
                    TC_COMMIT_MC_CG2(sb + OFF_EMPTY + 8 * cs);
                    if (chunk == NCHUNK - 1)
                        TC_COMMIT_MC_CG2(sb + OFF_ACCDONE + 8 * b);
                }
                if (++cs == STAGES) { cs = 0; cp ^= 1; }
            }
        }
    } else if (wid >= 2) {
        // ------- epilogue (both CTAs): 4 warps, own TMEM half -------
        const int sp = wid & 3;                 // TMEM subpartition
        uint32_t tIdx = 0;
        for (int t = clu; t < NTILES; t += nClusters, tIdx++) {
            const int b = tIdx & 1;
            const int nIdx = t & 7;
            const int mIdx = (t >> 3) & 31;
            const int d    = t >> 8;
            const int nB = nIdx * BN;

            mbar_wait_acq(sb + OFF_ACCDONE + 8 * b, (tIdx >> 1) & 1);
            TC_FENCE_AFTER();

            const int mRow = mIdx * BM + (int)rank * 128 + sp * 32 + lid;
            float* orow = out + ((size_t)d * M_TOT + mRow) * N_TOT + nB;
            const float* brow = bias + d * N_TOT + nB;
            const uint32_t tbase = tmem + b * 256;

#pragma unroll
            for (int nb = 0; nb < BN; nb += 32) {
                uint32_t r[32];
                TC_LD_X32(r, tbase + nb);
                TC_WAIT_LD();
#pragma unroll
                for (int j = 0; j < 32; j += 4) {
                    const float4 bv = *reinterpret_cast<const float4*>(brow + nb + j);
                    float4 v;
                    v.x = __uint_as_float(r[j + 0]) + bv.x;
                    v.y = __uint_as_float(r[j + 1]) + bv.y;
                    v.z = __uint_as_float(r[j + 2]) + bv.z;
                    v.w = __uint_as_float(r[j + 3]) + bv.w;
                    *reinterpret_cast<float4*>(orow + nb + j) = v;
                }
            }
            TC_FENCE_BEFORE();
            if (lid == 0)
                MBAR_ARRIVE_RANK0(sb + OFF_ACCFREE + 8 * b);
        }
    }

    __syncthreads();
    if (tid == 0) {
#pragma unroll
        for (int s = 0; s < STAGES; s++) {
            MBAR_INVAL(sb + OFF_FULL + 8 * s);
            MBAR_INVAL(sb + OFF_EMPTY + 8 * s);
        }
#pragma unroll
        for (int b = 0; b < 2; b++) {
            MBAR_INVAL(sb + OFF_ACCDONE + 8 * b);
            MBAR_INVAL(sb + OFF_ACCFREE + 8 * b);
        }
    }
    __syncthreads();
    CLUSTER_SYNC();   // all cross-CTA traffic drained
    if (wid == 0) {
        TC_DEALLOC_CG2(tmem, 512);
    }
    CLUSTER_SYNC();
#endif // TC_OK
}

// ------------------------------ host launch --------------------------------
typedef CUresult (*PFN_encodeTiled)(CUtensorMap*, CUtensorMapDataType, cuuint32_t, void*,
                                    const cuuint64_t*, const cuuint64_t*, const cuuint32_t*,
                                    const cuuint32_t*, CUtensorMapInterleave, CUtensorMapSwizzle,
                                    CUtensorMapL2promotion, CUtensorMapFloatOOBfill);

static void make_map_bf16(PFN_encodeTiled enc, CUtensorMap* m, void* p,
                          uint64_t d0, uint64_t d1, uint64_t d2,
                          uint64_t s1b, uint64_t s2b, uint32_t b0, uint32_t b1) {
    cuuint64_t dims[3] = {d0, d1, d2};
    cuuint64_t strides[2] = {s1b, s2b};
    cuuint32_t box[3] = {b0, b1, 1};
    cuuint32_t es[3] = {1, 1, 1};
    enc(m, CU_TENSOR_MAP_DATA_TYPE_BFLOAT16, 3, p, dims, strides, box, es,
        CU_TENSOR_MAP_INTERLEAVE_NONE, CU_TENSOR_MAP_SWIZZLE_128B,
        CU_TENSOR_MAP_L2_PROMOTION_L2_128B, CU_TENSOR_MAP_FLOAT_OOB_FILL_NONE);
}

extern "C" void kernel_launch(void* const* d_in, const int* in_sizes, int n_in,
                              void* d_out, int out_size) {
    const float* x    = (const float*)d_in[0];
    const float* W    = (const float*)d_in[1];
    const float* bias = (const float*)d_in[2];
    float* out        = (float*)d_out;

    void *pAh, *pAl, *pBh, *pBl;
    cudaGetSymbolAddress(&pAh, g_Ah);
    cudaGetSymbolAddress(&pAl, g_Al);
    cudaGetSymbolAddress(&pBh, g_Bh);
    cudaGetSymbolAddress(&pBl, g_Bl);

    void* fp = nullptr;
    cudaDriverEntryPointQueryResult qr;
    cudaGetDriverEntryPoint("cuTensorMapEncodeTiled", &fp, cudaEnableDefault, &qr);
    PFN_encodeTiled enc = (PFN_encodeTiled)fp;

    CUtensorMap mAh, mAl, mBh, mBl;
    // A: dims {K, M, 1}; box {64, 128} (one CTA's half)
    make_map_bf16(enc, &mAh, pAh, K_TOT, M_TOT, 1,
                  (uint64_t)K_TOT * 2, (uint64_t)M_TOT * K_TOT * 2, KB, 128);
    make_map_bf16(enc, &mAl, pAl, K_TOT, M_TOT, 1,
                  (uint64_t)K_TOT * 2, (uint64_t)M_TOT * K_TOT * 2, KB, 128);
    // B: dims {K, N, D}; box {64, 128} (one CTA's N-half)
    make_map_bf16(enc, &mBh, pBh, K_TOT, N_TOT, D_TOT,
                  (uint64_t)K_TOT * 2, (uint64_t)N_TOT * K_TOT * 2, KB, 128);
    make_map_bf16(enc, &mBl, pBl, K_TOT, N_TOT, D_TOT,
                  (uint64_t)K_TOT * 2, (uint64_t)N_TOT * K_TOT * 2, KB, 128);

    split_x_kernel<<<(D_TOT * M_TOT * 512 / 4) / 256, 256>>>(
        x, (__nv_bfloat16*)pAh, (__nv_bfloat16*)pAl);
    split_w_kernel<<<dim3(2048 / 32, 512 / 32, 16), dim3(32, 8)>>>(
        W, (__nv_bfloat16*)pBh, (__nv_bfloat16*)pBl);

    int dev = 0, sms = 148;
    cudaGetDevice(&dev);
    cudaDeviceGetAttribute(&sms, cudaDevAttrMultiProcessorCount, dev);
    int nBlocks = sms & ~1;            // even (cluster size 2)
    int nClusters = nBlocks / 2;

    cudaFuncSetAttribute(tp_gemm_kernel, cudaFuncAttributeMaxDynamicSharedMemorySize,
                         SMEM_TOTAL);
    tp_gemm_kernel<<<nBlocks, 192, SMEM_TOTAL>>>(mAh, mAl, mBh, mBl, bias, out, nClusters);
}

// round 9
// speedup vs baseline: 1.4924x; 1.2752x over previous
#include <cuda_runtime.h>
#include <cuda.h>
#include <cuda_bf16.h>
#include <cuda_fp8.h>
#include <cstdint>

// ---------------------------------------------------------------------------
// TPAsyncDense on tcgen05, persistent cg2 clusters, mixed bf16/fp8 split GEMM:
//   y[d] = sum_i x_i @ W[d,i] + b[d]
// A = Ah(bf16) + Al;  B = Bh(bf16) + Bl.
//   main:  Ah*Bh              kind::f16  (4 k-steps/chunk @128cyc cg2)
//   cross: Al*Bh8 + Ah'*Bl'   kind::f8f6f4 e5m2 (4 k-steps @64cyc), where
//          Ah' = Ah*2^-6, Bl' = Bl*2^6  (product scale 1 -> same accumulator)
// fp8 operands K-concatenated: A8 = [Al | Ah'], B8 = [Bh8 | Bl'] -> one
// SW128 16KB tile each; chunk = 4x16KB TMA loads (same traffic as R8),
// chunk MMA cycles 768 vs 1536. Ping-pong TMEM epilogue overlap preserved.
// ---------------------------------------------------------------------------

#if defined(__CUDA_ARCH_FEAT_SM103_ALL) || defined(__CUDA_ARCH_FEAT_SM100_ALL) || \
    defined(__CUDA_ARCH_SPECIFIC__) || defined(__CUDA_ARCH_FAMILY_SPECIFIC__)
#define TC_OK 1
#else
#define TC_OK 0
#endif

#define M_TOT 8192
#define N_TOT 2048
#define K_TOT 2048
#define D_TOT 4

#define BM 256                     // per cluster (128 per CTA)
#define BN 256
#define KB 64                      // true-K elems per chunk
#define NCHUNK 32                  // 2048/64
#define STAGES 3
#define NTILES (D_TOT * (M_TOT / BM) * (N_TOT / BN))   // 1024

#define OFF_TMEM     0
#define OFF_FULL     16            // 3 x 8B
#define OFF_EMPTY    40            // 3 x 8B
#define OFF_ACCDONE  64            // 2 x 8B
#define OFF_ACCFREE  80            // 2 x 8B
#define OP_BYTES     16384         // 128 rows x 128B
#define STG_BYTES    (4 * OP_BYTES)                 // 65536
#define OFF_STG      1024
#define SMEM_TOTAL   (OFF_STG + STAGES * STG_BYTES) // 197632
#define CHUNK_TX     (2 * STG_BYTES)                // both CTAs -> leader bar

#define SO_AH 0
#define SO_BH OP_BYTES
#define SO_A8 (2 * OP_BYTES)
#define SO_B8 (3 * OP_BYTES)

// cg2 idesc, M=256, N=256, D=fp32. atype/btype: BF16=1 under kind::f16,
// E5M2=1 under kind::f8f6f4 (same field positions).
#define IDESC_BF16 ((1u<<4) | (1u<<7) | (1u<<10) | (32u<<17) | (16u<<24))
#define IDESC_F8   ((1u<<4) | (1u<<7) | (1u<<10) | (32u<<17) | (16u<<24))

static constexpr uint64_t DESC_BASE_SW128 =
    (uint64_t(2) << 61) | (uint64_t(1) << 46) | (uint64_t(64) << 32) | (uint64_t(1) << 16);
#define DK 2                       // 32B k-step = 2 desc units (bf16 & fp8)

// ------------------------- scratch (static device mem) ---------------------
__device__ __align__(1024) __nv_bfloat16 g_Ah[(size_t)M_TOT * K_TOT];
__device__ __align__(1024) __nv_bfloat16 g_Bh[(size_t)D_TOT * N_TOT * K_TOT];
__device__ __align__(1024) uint8_t g_A8[(size_t)M_TOT * K_TOT * 2];            // [m][chunk*128+j]
__device__ __align__(1024) uint8_t g_B8[(size_t)D_TOT * N_TOT * K_TOT * 2];    // [d][n][chunk*128+j]

// ------------------------------ PTX helpers --------------------------------
__device__ __forceinline__ uint32_t smem_u32(const void* p) {
    uint32_t a;
    asm("{ .reg .u64 t; cvta.to.shared.u64 t, %1; cvt.u32.u64 %0, t; }" : "=r"(a) : "l"(p));
    return a;
}
__device__ __forceinline__ uint32_t elect_one() {
    uint32_t pred;
    asm volatile("{\n\t.reg .pred p;\n\telect.sync _|p, 0xFFFFFFFF;\n\tselp.b32 %0, 1, 0, p;\n\t}"
                 : "=r"(pred));
    return pred;
}
__device__ __forceinline__ uint32_t cluster_rank() {
    uint32_t r;
    asm("mov.u32 %0, %%cluster_ctarank;" : "=r"(r));
    return r;
}
#define CLUSTER_SYNC() do { \
    asm volatile("barrier.cluster.arrive.aligned;" ::: "memory"); \
    asm volatile("barrier.cluster.wait.aligned;" ::: "memory"); \
} while (0)

#define MBAR_INIT(addr, cnt) \
    asm volatile("mbarrier.init.shared.b64 [%0], %1;" :: "r"(addr), "r"(cnt) : "memory")
#define MBAR_INVAL(addr) \
    asm volatile("mbarrier.inval.shared.b64 [%0];" :: "r"(addr) : "memory")
#define MBAR_EXPECT_TX(addr, bytes) \
    asm volatile("mbarrier.arrive.expect_tx.shared.b64 _, [%0], %1;" :: "r"(addr), "r"(bytes) : "memory")
#define MBAR_ARRIVE_RANK0(addr) \
    asm volatile("{\n\t.reg .b32 ra;\n\tmapa.shared::cluster.u32 ra, %0, 0;\n\t" \
                 "mbarrier.arrive.shared::cluster.b64 _, [ra];\n\t}" \
                 :: "r"(addr) : "memory")

__device__ __forceinline__ void mbar_wait_acq(uint32_t mbar, uint32_t parity) {
    asm volatile(
        "{\n\t.reg .pred P1;\n\t"
        "WAIT_LOOP_%=:\n\t"
        "mbarrier.try_wait.parity.acquire.cta.shared::cta.b64 P1, [%0], %1, 0x989680;\n\t"
        "@P1 bra.uni WAIT_DONE_%=;\n\t"
        "bra.uni WAIT_LOOP_%=;\n\t"
        "WAIT_DONE_%=:\n\t}"
        :: "r"(mbar), "r"(parity) : "memory");
}
__device__ __forceinline__ void mbar_wait_rel(uint32_t mbar, uint32_t parity) {
    asm volatile(
        "{\n\t.reg .pred P1;\n\t"
        "WAIT_LOOP_%=:\n\t"
        "mbarrier.try_wait.parity.relaxed.cta.shared::cta.b64 P1, [%0], %1, 0x989680;\n\t"
        "@P1 bra.uni WAIT_DONE_%=;\n\t"
        "bra.uni WAIT_LOOP_%=;\n\t"
        "WAIT_DONE_%=:\n\t}"
        :: "r"(mbar), "r"(parity) : "memory");
}

#if TC_OK
__device__ __forceinline__ void tma_load_cg2(uint32_t smem_dst, const CUtensorMap* map,
                                             int cx, int cy, int cz, uint32_t mbar) {
    asm volatile(
        "{\n\t.reg .b32 lb;\n\t"
        "and.b32 lb, %5, 0xFEFFFFFF;\n\t"
        "cp.async.bulk.tensor.3d.cta_group::2.shared::cluster.global"
        ".tile.mbarrier::complete_tx::bytes [%0], [%1, {%2, %3, %4}], [lb];\n\t}"
        :: "r"(smem_dst), "l"(map), "r"(cx), "r"(cy), "r"(cz), "r"(mbar) : "memory");
}

__device__ __forceinline__ void mma_f16_cg2(uint32_t dtm, uint64_t adesc, uint64_t bdesc,
                                            uint32_t idesc, uint32_t en) {
    asm volatile(
        "{\n\t.reg .pred p;\n\tsetp.ne.u32 p, %5, 0;\n\t"
        "tcgen05.mma.cta_group::2.kind::f16 [%0], %1, %2, %3, "
        "{%4, %4, %4, %4, %4, %4, %4, %4}, p;\n\t}"
        :: "r"(dtm), "l"(adesc), "l"(bdesc), "r"(idesc), "r"(0u), "r"(en) : "memory");
}
__device__ __forceinline__ void mma_f8_cg2(uint32_t dtm, uint64_t adesc, uint64_t bdesc,
                                           uint32_t idesc, uint32_t en) {
    asm volatile(
        "{\n\t.reg .pred p;\n\tsetp.ne.u32 p, %5, 0;\n\t"
        "tcgen05.mma.cta_group::2.kind::f8f6f4 [%0], %1, %2, %3, "
        "{%4, %4, %4, %4, %4, %4, %4, %4}, p;\n\t}"
        :: "r"(dtm), "l"(adesc), "l"(bdesc), "r"(idesc), "r"(0u), "r"(en) : "memory");
}

#define TC_ALLOC_CG2(smem_addr, cols) \
    asm volatile("tcgen05.alloc.cta_group::2.sync.aligned.shared::cta.b32 [%0], %1;" \
                 :: "r"(smem_addr), "r"(cols) : "memory")
#define TC_DEALLOC_CG2(tmem, cols) \
    asm volatile("tcgen05.dealloc.cta_group::2.sync.aligned.b32 %0, %1;" :: "r"(tmem), "r"(cols))
#define TC_RELINQ_CG2() \
    asm volatile("tcgen05.relinquish_alloc_permit.cta_group::2.sync.aligned;")
#define TC_COMMIT_MC_CG2(mbar) \
    asm volatile("tcgen05.commit.cta_group::2.mbarrier::arrive::one.shared::cluster" \
                 ".multicast::cluster.b64 [%0], %1;" \
                 :: "r"(mbar), "h"((uint16_t)0x3) : "memory")
#define TC_FENCE_AFTER() asm volatile("tcgen05.fence::after_thread_sync;" ::: "memory")
#define TC_FENCE_BEFORE() asm volatile("tcgen05.fence::before_thread_sync;" ::: "memory")
#define TC_WAIT_LD() asm volatile("tcgen05.wait::ld.sync.aligned;" ::: "memory")

#define TC_LD_X32(r, tm) \
    asm volatile( \
        "tcgen05.ld.sync.aligned.32x32b.x32.b32 " \
        "{%0, %1, %2, %3, %4, %5, %6, %7, " \
        " %8, %9, %10, %11, %12, %13, %14, %15, " \
        " %16, %17, %18, %19, %20, %21, %22, %23, " \
        " %24, %25, %26, %27, %28, %29, %30, %31}, [%32];" \
        : "=r"((r)[0]),  "=r"((r)[1]),  "=r"((r)[2]),  "=r"((r)[3]), \
          "=r"((r)[4]),  "=r"((r)[5]),  "=r"((r)[6]),  "=r"((r)[7]), \
          "=r"((r)[8]),  "=r"((r)[9]),  "=r"((r)[10]), "=r"((r)[11]), \
          "=r"((r)[12]), "=r"((r)[13]), "=r"((r)[14]), "=r"((r)[15]), \
          "=r"((r)[16]), "=r"((r)[17]), "=r"((r)[18]), "=r"((r)[19]), \
          "=r"((r)[20]), "=r"((r)[21]), "=r"((r)[22]), "=r"((r)[23]), \
          "=r"((r)[24]), "=r"((r)[25]), "=r"((r)[26]), "=r"((r)[27]), \
          "=r"((r)[28]), "=r"((r)[29]), "=r"((r)[30]), "=r"((r)[31]) \
        : "r"(tm))
#endif // TC_OK

// ------------------------------ fused prep ---------------------------------
__device__ __forceinline__ uint8_t to_e5m2(float v) {
    return (uint8_t)__nv_cvt_float_to_fp8(v, __NV_SATFINITE, __NV_E5M2);
}

// blocks [0, 16384): x-split.  blocks [16384, 32768): W-split+transpose.
__global__ void prep_kernel(const float* __restrict__ x,
                            const float* __restrict__ W,
                            __nv_bfloat16* __restrict__ Ah,
                            uint8_t* __restrict__ A8,
                            __nv_bfloat16* __restrict__ Bh,
                            uint8_t* __restrict__ B8) {
    const int tid = threadIdx.x;
    if (blockIdx.x < 16384) {
        // ---- x: [4][8192][512] f32 -> Ah bf16 [8192][2048], A8 packed fp8 ----
        size_t t = (size_t)blockIdx.x * 256 + tid;
        size_t e = t * 4;
        int i = (int)(e >> 22);
        int m = (int)((e >> 9) & 8191);
        int k = (int)(e & 511);
        float4 v = reinterpret_cast<const float4*>(x)[t];
        const int kg = i * 512 + k;                 // global K, 4-aligned
        ushort4 h;
        uchar4 lo, hi6;
        float vv[4] = {v.x, v.y, v.z, v.w};
        unsigned short hs[4];
        uint8_t ls[4], hs6[4];
#pragma unroll
        for (int j = 0; j < 4; j++) {
            __nv_bfloat16 hb = __float2bfloat16_rn(vv[j]);
            float head = __bfloat162float(hb);
            hs[j] = *reinterpret_cast<unsigned short*>(&hb);
            ls[j]  = to_e5m2(vv[j] - head);          // Al
            hs6[j] = to_e5m2(head * 0.015625f);      // Ah * 2^-6
        }
        h = make_ushort4(hs[0], hs[1], hs[2], hs[3]);
        lo = make_uchar4(ls[0], ls[1], ls[2], ls[3]);
        hi6 = make_uchar4(hs6[0], hs6[1], hs6[2], hs6[3]);
        *reinterpret_cast<ushort4*>(Ah + (size_t)m * 2048 + kg) = h;
        size_t a8base = (size_t)m * 4096 + (size_t)(kg >> 6) * 128 + (kg & 63);
        *reinterpret_cast<uchar4*>(A8 + a8base) = lo;
        *reinterpret_cast<uchar4*>(A8 + a8base + 64) = hi6;
    } else {
        // ---- W: [4][4][512][2048] -> Bh bf16 [4][n][kg] (transpose), B8 fp8 ----
        __shared__ float tile[32][33];
        const int bid2 = blockIdx.x - 16384;
        const int n0 = (bid2 & 63) * 32;
        const int k0 = ((bid2 >> 6) & 15) * 32;
        const int di = bid2 >> 10;
        const int d = di >> 2, i = di & 3;
        const int tx = tid & 31, ty = tid >> 5;     // 32 x 8
        const float* Wdi = W + (size_t)di * 512 * 2048;
#pragma unroll
        for (int j = 0; j < 32; j += 8)
            tile[ty + j][tx] = Wdi[(size_t)(k0 + ty + j) * 2048 + n0 + tx];
        __syncthreads();
        size_t obase = (size_t)d * 2048 * 2048;
        size_t b8dbase = (size_t)d * 2048 * 4096;
#pragma unroll
        for (int j = 0; j < 32; j += 8) {
            float v = tile[tx][ty + j];
            __nv_bfloat16 hb = __float2bfloat16_rn(v);
            float head = __bfloat162float(hb);
            const int n = n0 + ty + j;
            const int kg = i * 512 + k0 + tx;
            *reinterpret_cast<unsigned short*>(
                reinterpret_cast<unsigned short*>(Bh) + obase + (size_t)n * 2048 + kg) =
                *reinterpret_cast<unsigned short*>(&hb);
            size_t b8base = b8dbase + (size_t)n * 4096 + (size_t)(kg >> 6) * 128 + (kg & 63);
            B8[b8base]      = to_e5m2(head);                    // Bh8
            B8[b8base + 64] = to_e5m2((v - head) * 64.0f);      // Bl * 2^6
        }
    }
}

// ------------------------------ GEMM kernel --------------------------------
__global__ __launch_bounds__(192, 1) __cluster_dims__(2, 1, 1)
void tp_gemm_kernel(const __grid_constant__ CUtensorMap tmAh,
                    const __grid_constant__ CUtensorMap tmBh,
                    const __grid_constant__ CUtensorMap tmA8,
                    const __grid_constant__ CUtensorMap tmB8,
                    const float* __restrict__ bias,
                    float* __restrict__ out,
                    int nClusters) {
#if TC_OK
    extern __shared__ char smem[];
    const uint32_t sb = smem_u32(smem);
    const int tid = threadIdx.x;
    const int wid = tid >> 5;
    const int lid = tid & 31;
    const uint32_t rank = cluster_rank();
    const int clu = (int)(blockIdx.x >> 1);

    if (wid == 0) {
        TC_ALLOC_CG2(sb + OFF_TMEM, 512);
        TC_RELINQ_CG2();
    }
    if (tid == 0) {
#pragma unroll
        for (int s = 0; s < STAGES; s++) {
            MBAR_INIT(sb + OFF_FULL + 8 * s, 1);
            MBAR_INIT(sb + OFF_EMPTY + 8 * s, 1);
        }
#pragma unroll
        for (int b = 0; b < 2; b++) {
            MBAR_INIT(sb + OFF_ACCDONE + 8 * b, 1);
            MBAR_INIT(sb + OFF_ACCFREE + 8 * b, 8);   // 4 warps x 2 CTAs
        }
    }
    __syncthreads();
    CLUSTER_SYNC();

    uint32_t tmem;
    asm volatile("ld.shared.b32 %0, [%1];" : "=r"(tmem) : "r"(sb + OFF_TMEM));

    if (wid == 0) {
        // ------- producer (both CTAs): cg2 TMA loads of own halves -------
        int ps = 0; uint32_t pp = 1;
        for (int t = clu; t < NTILES; t += nClusters) {
            const int nIdx = t & 7;
            const int mIdx = (t >> 3) & 31;
            const int d    = t >> 8;
            const int mRow = mIdx * BM + (int)rank * 128;
            const int nRow = nIdx * BN + (int)rank * 128;
            for (int chunk = 0; chunk < NCHUNK; chunk++) {
                mbar_wait_rel(sb + OFF_EMPTY + 8 * ps, pp);
                if (elect_one()) {
                    const uint32_t fb = sb + OFF_FULL + 8 * ps;
                    const uint32_t stg = sb + OFF_STG + ps * STG_BYTES;
                    const int kc = chunk * KB;          // bf16 K coord
                    const int kc8 = chunk * 128;        // fp8 byte coord
                    if (rank == 0)
                        MBAR_EXPECT_TX(fb, CHUNK_TX);
                    tma_load_cg2(stg + SO_AH, &tmAh, kc,  mRow, 0, fb);
                    tma_load_cg2(stg + SO_BH, &tmBh, kc,  nRow, d, fb);
                    tma_load_cg2(stg + SO_A8, &tmA8, kc8, mRow, 0, fb);
                    tma_load_cg2(stg + SO_B8, &tmB8, kc8, nRow, d, fb);
                }
                if (++ps == STAGES) { ps = 0; pp ^= 1; }
            }
        }
    } else if (wid == 1 && rank == 0) {
        // ------- consumer (rank 0 only): cg2 MMA issue -------
        int cs = 0; uint32_t cp = 0;
        uint32_t tIdx = 0;
        for (int t = clu; t < NTILES; t += nClusters, tIdx++) {
            const int b = tIdx & 1;
            mbar_wait_rel(sb + OFF_ACCFREE + 8 * b, ((tIdx >> 1) & 1) ^ 1);
            TC_FENCE_AFTER();
            const uint32_t dtm = tmem + b * 256;
            for (int chunk = 0; chunk < NCHUNK; chunk++) {
                mbar_wait_acq(sb + OFF_FULL + 8 * cs, cp);
                if (elect_one()) {
                    const uint32_t stg = sb + OFF_STG + cs * STG_BYTES;
                    const uint64_t adh = DESC_BASE_SW128 | ((uint64_t)((stg + SO_AH) >> 4) & 0x3FFF);
                    const uint64_t bdh = DESC_BASE_SW128 | ((uint64_t)((stg + SO_BH) >> 4) & 0x3FFF);
                    const uint64_t ad8 = DESC_BASE_SW128 | ((uint64_t)((stg + SO_A8) >> 4) & 0x3FFF);
                    const uint64_t bd8 = DESC_BASE_SW128 | ((uint64_t)((stg + SO_B8) >> 4) & 0x3FFF);
                    // main term: bf16, 4 k-steps (K=16 each)
#pragma unroll
                    for (int ks = 0; ks < 4; ks++) {
                        const uint32_t en = (chunk != 0 || ks != 0) ? 1u : 0u;
                        mma_f16_cg2(dtm, adh + ks * DK, bdh + ks * DK, IDESC_BF16, en);
                    }
                    // cross terms: e5m2, 4 k-steps (K=32 each) over [Al|Ah']x[Bh8|Bl']
#pragma unroll
                    for (int ks = 0; ks < 4; ks++) {
                        mma_f8_cg2(dtm, ad8 + ks * DK, bd8 + ks * DK, IDESC_F8, 1u);
                    }
                    TC_COMMIT_MC_CG2(sb + OFF_EMPTY + 8 * cs);
                    if (chunk == NCHUNK - 1)
                        TC_COMMIT_MC_CG2(sb + OFF_ACCDONE + 8 * b);
                }
                if (++cs == STAGES) { cs = 0; cp ^= 1; }
            }
        }
    } else if (wid >= 2) {
        // ------- epilogue (both CTAs): 4 warps, own TMEM half -------
        const int sp = wid & 3;
        uint32_t tIdx = 0;
        for (int t = clu; t < NTILES; t += nClusters, tIdx++) {
            const int b = tIdx & 1;
            const int nIdx = t & 7;
            const int mIdx = (t >> 3) & 31;
            const int d    = t >> 8;
            const int nB = nIdx * BN;

            mbar_wait_acq(sb + OFF_ACCDONE + 8 * b, (tIdx >> 1) & 1);
            TC_FENCE_AFTER();

            const int mRow = mIdx * BM + (int)rank * 128 + sp * 32 + lid;
            float* orow = out + ((size_t)d * M_TOT + mRow) * N_TOT + nB;
            const float* brow = bias + d * N_TOT + nB;
            const uint32_t tbase = tmem + b * 256;

#pragma unroll
            for (int nb = 0; nb < BN; nb += 32) {
                uint32_t r[32];
                TC_LD_X32(r, tbase + nb);
                TC_WAIT_LD();
#pragma unroll
                for (int j = 0; j < 32; j += 4) {
                    const float4 bv = *reinterpret_cast<const float4*>(brow + nb + j);
                    float4 v;
                    v.x = __uint_as_float(r[j + 0]) + bv.x;
                    v.y = __uint_as_float(r[j + 1]) + bv.y;
                    v.z = __uint_as_float(r[j + 2]) + bv.z;
                    v.w = __uint_as_float(r[j + 3]) + bv.w;
                    *reinterpret_cast<float4*>(orow + nb + j) = v;
                }
            }
            TC_FENCE_BEFORE();
            if (lid == 0)
                MBAR_ARRIVE_RANK0(sb + OFF_ACCFREE + 8 * b);
        }
    }

    __syncthreads();
    if (tid == 0) {
#pragma unroll
        for (int s = 0; s < STAGES; s++) {
            MBAR_INVAL(sb + OFF_FULL + 8 * s);
            MBAR_INVAL(sb + OFF_EMPTY + 8 * s);
        }
#pragma unroll
        for (int b = 0; b < 2; b++) {
            MBAR_INVAL(sb + OFF_ACCDONE + 8 * b);
            MBAR_INVAL(sb + OFF_ACCFREE + 8 * b);
        }
    }
    __syncthreads();
    CLUSTER_SYNC();
    if (wid == 0) {
        TC_DEALLOC_CG2(tmem, 512);
    }
    CLUSTER_SYNC();
#endif // TC_OK
}

// ------------------------------ host launch --------------------------------
typedef CUresult (*PFN_encodeTiled)(CUtensorMap*, CUtensorMapDataType, cuuint32_t, void*,
                                    const cuuint64_t*, const cuuint64_t*, const cuuint32_t*,
                                    const cuuint32_t*, CUtensorMapInterleave, CUtensorMapSwizzle,
                                    CUtensorMapL2promotion, CUtensorMapFloatOOBfill);

static void make_map(PFN_encodeTiled enc, CUtensorMap* m, void* p, CUtensorMapDataType dt,
                     uint64_t d0, uint64_t d1, uint64_t d2,
                     uint64_t s1b, uint64_t s2b, uint32_t b0, uint32_t b1) {
    cuuint64_t dims[3] = {d0, d1, d2};
    cuuint64_t strides[2] = {s1b, s2b};
    cuuint32_t box[3] = {b0, b1, 1};
    cuuint32_t es[3] = {1, 1, 1};
    enc(m, dt, 3, p, dims, strides, box, es,
        CU_TENSOR_MAP_INTERLEAVE_NONE, CU_TENSOR_MAP_SWIZZLE_128B,
        CU_TENSOR_MAP_L2_PROMOTION_L2_128B, CU_TENSOR_MAP_FLOAT_OOB_FILL_NONE);
}

extern "C" void kernel_launch(void* const* d_in, const int* in_sizes, int n_in,
                              void* d_out, int out_size) {
    const float* x    = (const float*)d_in[0];
    const float* W    = (const float*)d_in[1];
    const float* bias = (const float*)d_in[2];
    float* out        = (float*)d_out;

    void *pAh, *pBh, *pA8, *pB8;
    cudaGetSymbolAddress(&pAh, g_Ah);
    cudaGetSymbolAddress(&pBh, g_Bh);
    cudaGetSymbolAddress(&pA8, g_A8);
    cudaGetSymbolAddress(&pB8, g_B8);

    void* fp = nullptr;
    cudaDriverEntryPointQueryResult qr;
    cudaGetDriverEntryPoint("cuTensorMapEncodeTiled", &fp, cudaEnableDefault, &qr);
    PFN_encodeTiled enc = (PFN_encodeTiled)fp;

    CUtensorMap mAh, mBh, mA8, mB8;
    // bf16 A: dims {K, M, 1}; box {64, 128}
    make_map(enc, &mAh, pAh, CU_TENSOR_MAP_DATA_TYPE_BFLOAT16, K_TOT, M_TOT, 1,
             (uint64_t)K_TOT * 2, (uint64_t)M_TOT * K_TOT * 2, KB, 128);
    // bf16 B: dims {K, N, D}; box {64, 128}
    make_map(enc, &mBh, pBh, CU_TENSOR_MAP_DATA_TYPE_BFLOAT16, K_TOT, N_TOT, D_TOT,
             (uint64_t)K_TOT * 2, (uint64_t)N_TOT * K_TOT * 2, KB, 128);
    // fp8 A8: dims {4096 bytes, M, 1}; box {128, 128}
    make_map(enc, &mA8, pA8, CU_TENSOR_MAP_DATA_TYPE_UINT8, (uint64_t)K_TOT * 2, M_TOT, 1,
             (uint64_t)K_TOT * 2, (uint64_t)M_TOT * K_TOT * 2, 128, 128);
    // fp8 B8: dims {4096 bytes, N, D}; box {128, 128}
    make_map(enc, &mB8, pB8, CU_TENSOR_MAP_DATA_TYPE_UINT8, (uint64_t)K_TOT * 2, N_TOT, D_TOT,
             (uint64_t)K_TOT * 2, (uint64_t)N_TOT * K_TOT * 2, 128, 128);

    prep_kernel<<<32768, 256>>>(x, W, (__nv_bfloat16*)pAh, (uint8_t*)pA8,
                                (__nv_bfloat16*)pBh, (uint8_t*)pB8);

    int dev = 0, sms = 148;
    cudaGetDevice(&dev);
    cudaDeviceGetAttribute(&sms, cudaDevAttrMultiProcessorCount, dev);
    int nBlocks = sms & ~1;
    int nClusters = nBlocks / 2;

    cudaFuncSetAttribute(tp_gemm_kernel, cudaFuncAttributeMaxDynamicSharedMemorySize,
                         SMEM_TOTAL);
    tp_gemm_kernel<<<nBlocks, 192, SMEM_TOTAL>>>(mAh, mBh, mA8, mB8, bias, out, nClusters);
}